// round 6
// baseline (speedup 1.0000x reference)
#include <cuda_runtime.h>
#include <math.h>

#define NS 100000
#define H 128
#define NBLK 592            // 4 blocks/SM * 148 SMs
#define NTHREADS 256
#define WPB (NTHREADS / 32)
#define TILE 64             // rows per tile; 32KB -> L1-resident between phases
// 100000 = 592*168 + 544  ->  first 544 blocks take 169 rows, rest 168
#define BASE_ROWS 168
#define EXTRA 544

// Per-block partials: 0:P+.mu 1:P-.mu 2:P+.sig 3:P-.sig 4:S+ 5:S-
__device__ float g_part[6][NBLK];
__device__ int g_count = 0;

__device__ __forceinline__ float dot8(float4 a, float4 b, float4 x, float4 y) {
    return a.x * x.x + a.y * x.y + a.z * x.z + a.w * x.w +
           b.x * y.x + b.y * y.y + b.z * y.z + b.w * y.w;
}

__global__ __launch_bounds__(NTHREADS, 4) void fp_r6(
    const float* __restrict__ e, const float* __restrict__ q,
    const float* __restrict__ mu_w, const float* __restrict__ sigma_w,
    const float* __restrict__ w_key, const float* __restrict__ w_value,
    const float* __restrict__ mu_b, const float* __restrict__ sigma_b,
    float* __restrict__ out) {
    const int lane = threadIdx.x & 31;
    const int warp = threadIdx.x >> 5;
    const int sub  = lane & 15;
    const int half = lane >> 4;

    // this block's contiguous row chunk
    const int b = blockIdx.x;
    const int cnt   = BASE_ROWS + (b < EXTRA ? 1 : 0);
    const int start = b * BASE_ROWS + (b < EXTRA ? b : EXTRA);

    const float4* __restrict__ e4 = reinterpret_cast<const float4*>(e);
    const float4* __restrict__ q4 = reinterpret_cast<const float4*>(q);

    // q fragment for phase 1 (16-lane halves, both halves identical)
    float4 q0 = q4[sub * 2 + 0];
    float4 q1 = q4[sub * 2 + 1];
    float qn = dot8(q0, q1, q0, q1);
#pragma unroll
    for (int o = 8; o > 0; o >>= 1) qn += __shfl_xor_sync(0xffffffffu, qn, o);
    const float rq = rsqrtf(qn);

    __shared__ float cbuf[TILE];
    __shared__ float wsum[WPB][6];
    __shared__ int is_last;

    // phase-2 accumulators: lane owns columns lane*4 .. lane*4+3
    float pp0 = 0.f, pp1 = 0.f, pp2 = 0.f, pp3 = 0.f;
    float pm0 = 0.f, pm1 = 0.f, pm2 = 0.f, pm3 = 0.f;
    float sp = 0.f, sm = 0.f;

    for (int tb = 0; tb < cnt; tb += TILE) {
        const int tcnt = (cnt - tb < TILE) ? (cnt - tb) : TILE;

        // ── Phase 1: cosine per row (also pulls tile into L1) ──
        for (int pr = warp; pr * 2 < tcnt; pr += WPB) {
            int rl = pr * 2 + half;
            int rlc = (rl < tcnt) ? rl : (tcnt - 1);   // clamp: keep all lanes in shuffles
            const int r = start + tb + rlc;
            float4 a0 = e4[(size_t)r * 32 + sub * 2];
            float4 a1 = e4[(size_t)r * 32 + sub * 2 + 1];
            float d = dot8(a0, a1, q0, q1);
            float n = dot8(a0, a1, a0, a1);
#pragma unroll
            for (int o = 8; o > 0; o >>= 1) {
                d += __shfl_xor_sync(0xffffffffu, d, o);
                n += __shfl_xor_sync(0xffffffffu, n, o);
            }
            float c = d * rsqrtf(n) * rq;
            if (sub == 0 && rl < tcnt) cbuf[rl] = c;
        }
        __syncthreads();

        // ── Phase 2: accumulate P+/P- from L1-hot rows, shuffle-free ──
        for (int r0 = warp * 4; r0 < tcnt; r0 += WPB * 4) {
#pragma unroll
            for (int k = 0; k < 4; k++) {
                int rl = r0 + k;
                if (rl < tcnt) {
                    float4 v = e4[(size_t)(start + tb + rl) * 32 + lane];
                    float c = cbuf[rl];
                    float ap = fmaxf(c, 0.f), am = fmaxf(-c, 0.f);
                    sp += ap;  sm += am;
                    pp0 += ap * v.x;  pm0 += am * v.x;
                    pp1 += ap * v.y;  pm1 += am * v.y;
                    pp2 += ap * v.z;  pm2 += am * v.z;
                    pp3 += ap * v.w;  pm3 += am * v.w;
                }
            }
        }
        __syncthreads();   // cbuf reused next tile
    }

    // ── Epilogue: pre-dot lane's columns with mu_w / sigma_w ──
    float4 mw = reinterpret_cast<const float4*>(mu_w)[lane];
    float4 sw = reinterpret_cast<const float4*>(sigma_w)[lane];
    float t0 = pp0 * mw.x + pp1 * mw.y + pp2 * mw.z + pp3 * mw.w;
    float t1 = pm0 * mw.x + pm1 * mw.y + pm2 * mw.z + pm3 * mw.w;
    float t2 = pp0 * sw.x + pp1 * sw.y + pp2 * sw.z + pp3 * sw.w;
    float t3 = pm0 * sw.x + pm1 * sw.y + pm2 * sw.z + pm3 * sw.w;
#pragma unroll
    for (int o = 16; o > 0; o >>= 1) {
        t0 += __shfl_xor_sync(0xffffffffu, t0, o);
        t1 += __shfl_xor_sync(0xffffffffu, t1, o);
        t2 += __shfl_xor_sync(0xffffffffu, t2, o);
        t3 += __shfl_xor_sync(0xffffffffu, t3, o);
        sp += __shfl_xor_sync(0xffffffffu, sp, o);
        sm += __shfl_xor_sync(0xffffffffu, sm, o);
    }
    if (lane == 0) {
        wsum[warp][0] = t0;
        wsum[warp][1] = t1;
        wsum[warp][2] = t2;
        wsum[warp][3] = t3;
        wsum[warp][4] = sp * 0.03125f;   // each of 32 lanes held the full row sum
        wsum[warp][5] = sm * 0.03125f;
    }
    __syncthreads();
    if (threadIdx.x < 6) {
        float s = 0.f;
#pragma unroll
        for (int w = 0; w < WPB; w++) s += wsum[w][threadIdx.x];
        g_part[threadIdx.x][b] = s;
    }
    __threadfence();
    __syncthreads();
    if (threadIdx.x == 0)
        is_last = (atomicAdd(&g_count, 1) == NBLK - 1) ? 1 : 0;
    __syncthreads();
    if (!is_last) return;

    // ── Last block: final 6-scalar reduce + the 8 outputs ──
    __shared__ float tot[6];
    if (warp < 6) {
        float s = 0.f;
#pragma unroll
        for (int i = 0; i < (NBLK + 31) / 32; i++) {
            int j = lane + i * 32;
            if (j < NBLK) s += __ldcg(&g_part[warp][j]);
        }
#pragma unroll
        for (int o = 16; o > 0; o >>= 1) s += __shfl_xor_sync(0xffffffffu, s, o);
        if (lane == 0) tot[warp] = s;
    }
    __syncthreads();
    if (threadIdx.x < 4) {
        const int t = threadIdx.x;
        const float Sp = fmaxf(tot[4], 1e-6f);
        const float Sm = fmaxf(tot[5], 1e-6f);
        float wk = w_key[t];
        float wv = w_value[t];
        bool pos = (wk > 0.f);
        float dmu = pos ? (tot[0] / Sp) : (tot[1] / Sm);
        float dsg = pos ? (tot[2] / Sp) : (tot[3] / Sm);
        float mu_z = wv * dmu + mu_b[0];
        float x = wv * dsg + sigma_b[0];
        float sig_z = fmaxf(x, 0.f) + log1pf(expf(-fabsf(x)));
        out[t] = mu_z;
        out[4 + t] = sig_z;
    }
    if (threadIdx.x == 0) g_count = 0;   // reset for next graph replay
}

extern "C" void kernel_launch(void* const* d_in, const int* in_sizes, int n_in,
                              void* d_out, int out_size) {
    const float* e       = (const float*)d_in[0];
    const float* w_key   = (const float*)d_in[1];
    const float* w_value = (const float*)d_in[2];
    const float* q       = (const float*)d_in[3];
    const float* mu_w    = (const float*)d_in[4];
    const float* mu_b    = (const float*)d_in[5];
    const float* sigma_w = (const float*)d_in[6];
    const float* sigma_b = (const float*)d_in[7];
    float* out = (float*)d_out;

    fp_r6<<<NBLK, NTHREADS>>>(e, q, mu_w, sigma_w, w_key, w_value, mu_b, sigma_b, out);
}